// round 2
// baseline (speedup 1.0000x reference)
#include <cuda_runtime.h>
#include <cuda_bf16.h>
#include <cstdint>

// MultiDepthLimitedMSELoss: per-row greedy matching of 8 outputs to 8 targets
// (sequential argmin of |out - t_i| with knockout -> finfo.max), then mean of
// squared matched distances, with targets == 0.0 contributing exactly 0.
//
// One lane per row. argmin via packed keys:
//   key_j = (bits(o_j - t_i) & 0x7FFFFFF8) | j          (single LOP3 per j)
// Unsigned min over keys yields both min |distance| (3 lsb truncated, ~5e-7
// rel err) and the first-min index (low bits), matching jnp.argmin tie-break.
// Loss term is key_distance^2 directly (when t != 0, (o_shfl - t)^2 = d^2),
// so the matched output value is never materialized.
// Deterministic two-kernel reduction (no float atomics, graph-replay stable).

#define BLOCKS   2048
#define THREADS  256

__device__ float g_partials[BLOCKS];

__global__ void __launch_bounds__(THREADS)
match_loss_kernel(const float* __restrict__ outs,
                  const float* __restrict__ tgts,
                  int n)  // n = number of rows
{
    const unsigned FULL = 0xffffffffu;
    const int tid     = blockIdx.x * THREADS + threadIdx.x;
    const int nthread = gridDim.x * THREADS;

    float acc = 0.0f;

    for (int row = tid; row < n; row += nthread) {
        const size_t base = (size_t)row << 3;   // row * 8 floats = 32 bytes
        // two float4 loads per tensor; warp covers 1024 contiguous bytes each
        const float4 o0 = *reinterpret_cast<const float4*>(outs + base);
        const float4 o1 = *reinterpret_cast<const float4*>(outs + base + 4);
        const float4 t0 = *reinterpret_cast<const float4*>(tgts + base);
        const float4 t1 = *reinterpret_cast<const float4*>(tgts + base + 4);

        float o[8] = { o0.x, o0.y, o0.z, o0.w, o1.x, o1.y, o1.z, o1.w };
        const float t[8] = { t0.x, t0.y, t0.z, t0.w, t1.x, t1.y, t1.z, t1.w };

#pragma unroll
        for (int i = 0; i < 8; ++i) {
            const float ti = t[i];

            // packed keys: abs-bits with low 3 bits replaced by index j.
            // (x & 0x7FFFFFF8) | j is one LOP3.
            unsigned kk[8];
#pragma unroll
            for (int j = 0; j < 8; ++j)
                kk[j] = (__float_as_uint(o[j] - ti) & 0x7FFFFFF8u) | (unsigned)j;

            unsigned a0 = min(kk[0], kk[1]);
            unsigned a1 = min(kk[2], kk[3]);
            unsigned a2 = min(kk[4], kk[5]);
            unsigned a3 = min(kk[6], kk[7]);
            a0 = min(a0, a1);
            a2 = min(a2, a3);
            const unsigned m = min(a0, a2);

            // knockout the (unique) winner: its key equals m exactly.
#pragma unroll
            for (int j = 0; j < 8; ++j)
                o[j] = (kk[j] == m) ? __uint_as_float(0x7f800000u) : o[j];

            const float bd = __uint_as_float(m & 0x7FFFFFF8u);  // |o_w - t_i|
            if (ti != 0.0f)        // IGNORE_VALUE == 0.0 -> zero contribution
                acc = fmaf(bd, bd, acc);
        }
    }

    // warp + block reduction (deterministic order)
#pragma unroll
    for (int s = 16; s > 0; s >>= 1)
        acc += __shfl_xor_sync(FULL, acc, s);

    __shared__ float sw[THREADS / 32];
    const int lane = threadIdx.x & 31;
    const int wib  = threadIdx.x >> 5;
    if (lane == 0) sw[wib] = acc;
    __syncthreads();
    if (threadIdx.x == 0) {
        float b = 0.0f;
#pragma unroll
        for (int i = 0; i < THREADS / 32; ++i) b += sw[i];
        g_partials[blockIdx.x] = b;
    }
}

__global__ void reduce_kernel(float* __restrict__ out, int n)
{
    __shared__ double sm[256];
    double s = 0.0;
    for (int i = threadIdx.x; i < BLOCKS; i += 256)
        s += (double)g_partials[i];
    sm[threadIdx.x] = s;
    __syncthreads();
#pragma unroll
    for (int st = 128; st > 0; st >>= 1) {
        if (threadIdx.x < st) sm[threadIdx.x] += sm[threadIdx.x + st];
        __syncthreads();
    }
    if (threadIdx.x == 0)
        out[0] = (float)(sm[0] / ((double)n * 8.0));
}

extern "C" void kernel_launch(void* const* d_in, const int* in_sizes, int n_in,
                              void* d_out, int out_size)
{
    const float* outputs = (const float*)d_in[0];
    const float* targets = (const float*)d_in[1];
    const int n = in_sizes[0] / 8;   // rows

    match_loss_kernel<<<BLOCKS, THREADS>>>(outputs, targets, n);
    reduce_kernel<<<1, 256>>>((float*)d_out, n);
}

// round 4
// speedup vs baseline: 1.0396x; 1.0396x over previous
#include <cuda_runtime.h>
#include <cuda_bf16.h>
#include <cstdint>

// MultiDepthLimitedMSELoss: per-row greedy matching of 8 outputs to 8 targets
// (sequential argmin of |out - t_i| with knockout -> +inf), then mean of
// squared matched distances; targets == 0.0 contribute exactly 0.
//
// One lane per row. argmin via packed integer keys:
//   key_j = (bits(o_j - t_i) & 0x7FFFFFF8) | j     (single LOP3 per j)
// Unsigned min over keys yields min |distance| (3 lsb truncated, ~5e-7 rel
// err) AND the first-min index in the low bits (matches jnp.argmin
// tie-break). Knockout compares full keys (kk[j] == m): unique by
// construction since index bits differ -> exactly one knockout per step.
// (Float-domain knockout without index bits is UNSAFE: bit-identical
// distances double-knock and exhaust the row -> inf. Seen in round 3.)
//
// Reduction fused into the main kernel via the last-block pattern
// (threadfence + atomic counter, fixed-order double sum: deterministic and
// graph-replay safe; counter self-resets).

#define BLOCKS   (148 * 16)   // 2368
#define THREADS  256

__device__ float    g_partials[BLOCKS];
__device__ unsigned g_count = 0;

__global__ void __launch_bounds__(THREADS)
match_loss_kernel(const float* __restrict__ outs,
                  const float* __restrict__ tgts,
                  float* __restrict__ result,
                  int n)  // n = number of rows
{
    const unsigned FULL = 0xffffffffu;
    const float INF = __uint_as_float(0x7f800000u);
    const int tid     = blockIdx.x * THREADS + threadIdx.x;
    const int nthread = gridDim.x * THREADS;

    float acc = 0.0f;

    for (int row = tid; row < n; row += nthread) {
        const size_t base = (size_t)row << 3;   // row * 8 floats
        // streaming loads (no reuse); warp covers 1024 contiguous B per tensor
        const float4 o0 = __ldcs(reinterpret_cast<const float4*>(outs + base));
        const float4 o1 = __ldcs(reinterpret_cast<const float4*>(outs + base + 4));
        const float4 t0 = __ldcs(reinterpret_cast<const float4*>(tgts + base));
        const float4 t1 = __ldcs(reinterpret_cast<const float4*>(tgts + base + 4));

        float o[8] = { o0.x, o0.y, o0.z, o0.w, o1.x, o1.y, o1.z, o1.w };
        const float t[8] = { t0.x, t0.y, t0.z, t0.w, t1.x, t1.y, t1.z, t1.w };

#pragma unroll
        for (int i = 0; i < 8; ++i) {
            const float ti = t[i];

            // packed keys: abs-bits with low 3 bits replaced by index j.
            // (x & 0x7FFFFFF8) | j is one LOP3.
            unsigned kk[8];
#pragma unroll
            for (int j = 0; j < 8; ++j)
                kk[j] = (__float_as_uint(o[j] - ti) & 0x7FFFFFF8u) | (unsigned)j;

            unsigned a0 = min(kk[0], kk[1]);
            unsigned a1 = min(kk[2], kk[3]);
            unsigned a2 = min(kk[4], kk[5]);
            unsigned a3 = min(kk[6], kk[7]);
            a0 = min(a0, a1);
            a2 = min(a2, a3);
            const unsigned m = min(a0, a2);

            // knockout the unique winner (index bits make keys distinct)
#pragma unroll
            for (int j = 0; j < 8; ++j)
                o[j] = (kk[j] == m) ? INF : o[j];

            const float bd = __uint_as_float(m & 0x7FFFFFF8u);  // |o_w - t_i|
            if (ti != 0.0f)        // IGNORE_VALUE == 0.0 -> zero contribution
                acc = fmaf(bd, bd, acc);
        }
    }

    // ---- warp + block reduction (fixed order, deterministic) ----
#pragma unroll
    for (int s = 16; s > 0; s >>= 1)
        acc += __shfl_xor_sync(FULL, acc, s);

    __shared__ float sw[THREADS / 32];
    __shared__ bool  isLast;
    const int lane = threadIdx.x & 31;
    const int wib  = threadIdx.x >> 5;
    if (lane == 0) sw[wib] = acc;
    __syncthreads();
    if (threadIdx.x == 0) {
        float b = 0.0f;
#pragma unroll
        for (int i = 0; i < THREADS / 32; ++i) b += sw[i];
        g_partials[blockIdx.x] = b;
        __threadfence();
        const unsigned prev = atomicAdd(&g_count, 1u);
        isLast = (prev == (unsigned)(gridDim.x - 1));
    }
    __syncthreads();

    // ---- last block finishes: fixed-order double sum over partials ----
    if (isLast) {
        __shared__ double sm[THREADS];
        double s = 0.0;
        for (int i = threadIdx.x; i < BLOCKS; i += THREADS)
            s += (double)g_partials[i];
        sm[threadIdx.x] = s;
        __syncthreads();
#pragma unroll
        for (int st = THREADS / 2; st > 0; st >>= 1) {
            if (threadIdx.x < st) sm[threadIdx.x] += sm[threadIdx.x + st];
            __syncthreads();
        }
        if (threadIdx.x == 0) {
            result[0] = (float)(sm[0] / ((double)n * 8.0));
            g_count = 0;   // reset for next graph replay
        }
    }
}

extern "C" void kernel_launch(void* const* d_in, const int* in_sizes, int n_in,
                              void* d_out, int out_size)
{
    const float* outputs = (const float*)d_in[0];
    const float* targets = (const float*)d_in[1];
    const int n = in_sizes[0] / 8;   // rows

    match_loss_kernel<<<BLOCKS, THREADS>>>(outputs, targets, (float*)d_out, n);
}

// round 5
// speedup vs baseline: 1.5370x; 1.4785x over previous
#include <cuda_runtime.h>
#include <cuda_bf16.h>
#include <cstdint>

// MultiDepthLimitedMSELoss: per-row greedy matching of 8 outputs to 8 targets
// (sequential argmin of |out - t_i|, matched output knocked out), then mean of
// squared matched distances; targets == 0.0 contribute exactly 0.
//
// One lane per row. argmin via packed integer keys over the LIVE set only:
//   key_j = (bits(o_j - t_i) & 0x7FFFFFF8) | j    (one LOP3; j = live position)
// Unsigned min gives min |distance| (3 lsb truncated, ~5e-7 rel err) AND the
// first-min live position (matches jnp.argmin tie-break, since compaction
// preserves order). Winner is then REMOVED by compacting the register array
// (o[j] = j<w ? o[j] : o[j+1]) instead of overwriting with +inf: step with k
// live elements costs ~4k-3 alu ops vs 31, halving total alu work (the
// measured bottleneck: alu pipe 75.1% at 81.3us).
// Exactly-one-removal is structural (index bits make keys unique) — the
// float-equality double-knockout failure of round 3 cannot occur.
//
// Reduction fused via last-block pattern (threadfence + atomic counter,
// fixed-order double sum; deterministic, graph-replay safe, self-resetting).

#define BLOCKS   (148 * 10)   // 1480: ~2 waves at 5 blocks/SM, grid-stride
#define THREADS  256

__device__ float    g_partials[BLOCKS];
__device__ unsigned g_count = 0;

__global__ void __launch_bounds__(THREADS)
match_loss_kernel(const float* __restrict__ outs,
                  const float* __restrict__ tgts,
                  float* __restrict__ result,
                  int n)  // n = number of rows
{
    const unsigned FULL = 0xffffffffu;
    const int tid     = blockIdx.x * THREADS + threadIdx.x;
    const int nthread = gridDim.x * THREADS;

    float acc = 0.0f;

    for (int row = tid; row < n; row += nthread) {
        const size_t base = (size_t)row << 3;   // row * 8 floats
        // streaming loads (no reuse); warp covers 1024 contiguous B per tensor
        const float4 o0 = __ldcs(reinterpret_cast<const float4*>(outs + base));
        const float4 o1 = __ldcs(reinterpret_cast<const float4*>(outs + base + 4));
        const float4 t0 = __ldcs(reinterpret_cast<const float4*>(tgts + base));
        const float4 t1 = __ldcs(reinterpret_cast<const float4*>(tgts + base + 4));

        float o[8] = { o0.x, o0.y, o0.z, o0.w, o1.x, o1.y, o1.z, o1.w };
        const float t[8] = { t0.x, t0.y, t0.z, t0.w, t1.x, t1.y, t1.z, t1.w };

#pragma unroll
        for (int i = 0; i < 8; ++i) {
            const int k = 8 - i;           // live element count (compile-time)
            const float ti = t[i];

            // packed keys for live elements only
            unsigned kk[8];
#pragma unroll
            for (int j = 0; j < k; ++j)
                kk[j] = (__float_as_uint(o[j] - ti) & 0x7FFFFFF8u) | (unsigned)j;

            // balanced min tree over k keys (in place)
#pragma unroll
            for (int s = 1; s < k; s <<= 1) {
#pragma unroll
                for (int j = 0; j + s < k; j += (s << 1))
                    kk[j] = min(kk[j], kk[j + s]);
            }
            const unsigned m = kk[0];
            const int w = (int)(m & 7u);    // winning live position (0..k-1)

            // loss term: min |distance| squared, skipped when target == 0
            const float bd  = __uint_as_float(m & 0x7FFFFFF8u);
            const float bd2 = (ti != 0.0f) ? bd : 0.0f;   // FSEL (pred-as-data)
            acc = fmaf(bd2, bd2, acc);

            // compact: remove live position w (order preserved)
#pragma unroll
            for (int j = 0; j < k - 1; ++j)
                o[j] = (j < w) ? o[j] : o[j + 1];
        }
    }

    // ---- warp + block reduction (fixed order, deterministic) ----
#pragma unroll
    for (int s = 16; s > 0; s >>= 1)
        acc += __shfl_xor_sync(FULL, acc, s);

    __shared__ float sw[THREADS / 32];
    __shared__ bool  isLast;
    const int lane = threadIdx.x & 31;
    const int wib  = threadIdx.x >> 5;
    if (lane == 0) sw[wib] = acc;
    __syncthreads();
    if (threadIdx.x == 0) {
        float b = 0.0f;
#pragma unroll
        for (int i = 0; i < THREADS / 32; ++i) b += sw[i];
        g_partials[blockIdx.x] = b;
        __threadfence();
        const unsigned prev = atomicAdd(&g_count, 1u);
        isLast = (prev == (unsigned)(gridDim.x - 1));
    }
    __syncthreads();

    // ---- last block finishes: fixed-order double sum over partials ----
    if (isLast) {
        __shared__ double sm[THREADS];
        double s = 0.0;
        for (int i = threadIdx.x; i < BLOCKS; i += THREADS)
            s += (double)g_partials[i];
        sm[threadIdx.x] = s;
        __syncthreads();
#pragma unroll
        for (int st = THREADS / 2; st > 0; st >>= 1) {
            if (threadIdx.x < st) sm[threadIdx.x] += sm[threadIdx.x + st];
            __syncthreads();
        }
        if (threadIdx.x == 0) {
            result[0] = (float)(sm[0] / ((double)n * 8.0));
            g_count = 0;   // reset for next graph replay
        }
    }
}

extern "C" void kernel_launch(void* const* d_in, const int* in_sizes, int n_in,
                              void* d_out, int out_size)
{
    const float* outputs = (const float*)d_in[0];
    const float* targets = (const float*)d_in[1];
    const int n = in_sizes[0] / 8;   // rows

    match_loss_kernel<<<BLOCKS, THREADS>>>(outputs, targets, (float*)d_out, n);
}